// round 1
// baseline (speedup 1.0000x reference)
#include <cuda_runtime.h>
#include <math.h>

#define NTOK 32768      // 32*32*32
#define CDIM 128
#define HEADS 8
#define HD 16
#define CF 512

// ---------------- scratch (device globals; no runtime allocation) ------------
__device__ float g_qkv [384 * NTOK];   // [j][n] j: 0-127 q, 128-255 k, 256-383 v
__device__ float g_attn[CDIM * NTOK];  // [c][n]
__device__ float g_x5  [CDIM * NTOK];  // [c][n] proj out
__device__ float g_t   [CDIM * NTOK];  // [c][n] normalized (FFN input + residual)
__device__ float g_hid [CF   * NTOK];  // [f][n]
__device__ float g_y   [CDIM * NTOK];  // [c][n] pre-final-IN

// ---------------- fused GEMM: out[j][n] = sum_k A[k][n]*W[j][k] + b[j] -------
// A k-major [Ktot][NTOK], W row-major [Jtot][Ktot], out [Jtot][NTOK].
// EPI: 0 = bias; 1 = gelu(bias+acc); 2 = residual R[j][n] + bias + acc
__device__ __forceinline__ float gelu_f(float x) {
    const float k0 = 0.7978845608028654f;   // sqrt(2/pi)
    const float k1 = 0.044715f;
    return 0.5f * x * (1.0f + tanhf(k0 * (x + k1 * x * x * x)));
}

template<int EPI>
__global__ __launch_bounds__(256)
void gemm_kn(const float* __restrict__ A, const float* __restrict__ W,
             const float* __restrict__ bias, const float* __restrict__ R,
             float* __restrict__ out, int Ktot)
{
    const int BM = 64, BJ = 128, KC = 64;
    __shared__ float As[KC][BM];     // 16 KB
    __shared__ float Ws[BJ][KC];     // 32 KB  (total 48 KB exactly)

    const int tid = threadIdx.x;
    const int m0  = blockIdx.x * BM;
    const int j0  = blockIdx.y * BJ;
    const int tm  = (tid & 15) << 2;   // 0..60
    const int tj  = (tid >> 4) << 3;   // 0..120

    float acc[8][4];
    #pragma unroll
    for (int a = 0; a < 8; a++)
        #pragma unroll
        for (int b = 0; b < 4; b++) acc[a][b] = 0.0f;

    for (int kc = 0; kc < Ktot; kc += KC) {
        // A tile: 4096 floats = 1024 float4, 4 per thread, coalesced over n
        #pragma unroll
        for (int i = 0; i < 4; i++) {
            int f  = tid + i * 256;
            int k  = f >> 4;
            int mq = (f & 15) << 2;
            *(float4*)&As[k][mq] =
                *(const float4*)&A[(size_t)(kc + k) * NTOK + m0 + mq];
        }
        // W tile: 8192 floats = 2048 float4, 8 per thread
        #pragma unroll
        for (int i = 0; i < 8; i++) {
            int f  = tid + i * 256;
            int j  = f >> 4;
            int kq = (f & 15) << 2;
            *(float4*)&Ws[j][kq] =
                *(const float4*)&W[(size_t)(j0 + j) * Ktot + kc + kq];
        }
        __syncthreads();

        #pragma unroll 2
        for (int c = 0; c < KC; c += 4) {
            float4 av[4];
            #pragma unroll
            for (int cc = 0; cc < 4; cc++)
                av[cc] = *(float4*)&As[c + cc][tm];
            #pragma unroll
            for (int jj = 0; jj < 8; jj++) {
                float4 w = *(float4*)&Ws[tj + jj][c];
                #pragma unroll
                for (int cc = 0; cc < 4; cc++) {
                    float ws = ((float*)&w)[cc];
                    float4 a = av[cc];
                    acc[jj][0] = fmaf(ws, a.x, acc[jj][0]);
                    acc[jj][1] = fmaf(ws, a.y, acc[jj][1]);
                    acc[jj][2] = fmaf(ws, a.z, acc[jj][2]);
                    acc[jj][3] = fmaf(ws, a.w, acc[jj][3]);
                }
            }
        }
        __syncthreads();
    }

    #pragma unroll
    for (int jj = 0; jj < 8; jj++) {
        int j = j0 + tj + jj;
        float b = bias[j];
        float4 v;
        float* vp = (float*)&v;
        #pragma unroll
        for (int mm = 0; mm < 4; mm++) vp[mm] = acc[jj][mm] + b;
        if (EPI == 1) {
            #pragma unroll
            for (int mm = 0; mm < 4; mm++) vp[mm] = gelu_f(vp[mm]);
        }
        if (EPI == 2) {
            float4 r = *(const float4*)&R[(size_t)j * NTOK + m0 + tm];
            v.x += r.x; v.y += r.y; v.z += r.z; v.w += r.w;
        }
        *(float4*)&out[(size_t)j * NTOK + m0 + tm] = v;
    }
}

// ---------------- neighborhood attention (K=3, 27 taps) ----------------------
__global__ __launch_bounds__(256)
void natten_kernel(const float* __restrict__ qkv,
                   const float* __restrict__ rpb,
                   float* __restrict__ out)
{
    // block = one (ih, iw) row of 32 z voxels x 8 heads
    const int lane = threadIdx.x & 31;
    const int h    = threadIdx.x >> 5;
    const int ih   = blockIdx.x >> 5;
    const int iw   = blockIdx.x & 31;
    const int iz   = lane;
    const int n    = (ih * 32 + iw) * 32 + iz;

    int sh = ih - 1; sh = sh < 0 ? 0 : (sh > 29 ? 29 : sh);
    int sw = iw - 1; sw = sw < 0 ? 0 : (sw > 29 ? 29 : sw);
    int sz = iz - 1; sz = sz < 0 ? 0 : (sz > 29 ? 29 : sz);

    const float scale = 0.25f;   // hd^-0.5 = 16^-0.5
    float q[HD];
    #pragma unroll
    for (int d = 0; d < HD; d++)
        q[d] = qkv[(size_t)(h * HD + d) * NTOK + n] * scale;

    float lg[27];
    float mx = -1e30f;
    #pragma unroll
    for (int a = 0; a < 3; a++)
    #pragma unroll
    for (int b = 0; b < 3; b++)
    #pragma unroll
    for (int c = 0; c < 3; c++) {
        int nh = sh + a, nw = sw + b, nz = sz + c;
        int nn = (nh * 32 + nw) * 32 + nz;
        float s = 0.0f;
        #pragma unroll
        for (int d = 0; d < HD; d++)
            s = fmaf(q[d], qkv[(size_t)(CDIM + h * HD + d) * NTOK + nn], s);
        int rh = nh - ih + 2, rw = nw - iw + 2, rz = nz - iz + 2;
        s += rpb[((h * 5 + rh) * 5 + rw) * 5 + rz];
        lg[(a * 3 + b) * 3 + c] = s;
        mx = fmaxf(mx, s);
    }

    float denom = 0.0f;
    #pragma unroll
    for (int i = 0; i < 27; i++) { lg[i] = __expf(lg[i] - mx); denom += lg[i]; }
    const float inv = 1.0f / denom;

    float o[HD];
    #pragma unroll
    for (int d = 0; d < HD; d++) o[d] = 0.0f;
    #pragma unroll
    for (int a = 0; a < 3; a++)
    #pragma unroll
    for (int b = 0; b < 3; b++)
    #pragma unroll
    for (int c = 0; c < 3; c++) {
        int nh = sh + a, nw = sw + b, nz = sz + c;
        int nn = (nh * 32 + nw) * 32 + nz;
        float w = lg[(a * 3 + b) * 3 + c] * inv;
        #pragma unroll
        for (int d = 0; d < HD; d++)
            o[d] = fmaf(w, qkv[(size_t)(2 * CDIM + h * HD + d) * NTOK + nn], o[d]);
    }
    #pragma unroll
    for (int d = 0; d < HD; d++)
        out[(size_t)(h * HD + d) * NTOK + n] = o[d];
}

// ---------------- instance norm over N per channel ----------------------------
__global__ __launch_bounds__(256)
void inorm_kernel(const float* __restrict__ in, float* __restrict__ out)
{
    const int c = blockIdx.x;
    const float4* p = (const float4*)(in + (size_t)c * NTOK);
    float s = 0.0f, s2 = 0.0f;
    for (int i = threadIdx.x; i < NTOK / 4; i += 256) {
        float4 v = p[i];
        s  += v.x + v.y + v.z + v.w;
        s2 += v.x * v.x + v.y * v.y + v.z * v.z + v.w * v.w;
    }
    __shared__ float rs[256], rq[256];
    rs[threadIdx.x] = s; rq[threadIdx.x] = s2;
    __syncthreads();
    for (int st = 128; st > 0; st >>= 1) {
        if (threadIdx.x < st) {
            rs[threadIdx.x] += rs[threadIdx.x + st];
            rq[threadIdx.x] += rq[threadIdx.x + st];
        }
        __syncthreads();
    }
    __shared__ float s_mean, s_rstd;
    if (threadIdx.x == 0) {
        float m = rs[0] * (1.0f / NTOK);
        float v = rq[0] * (1.0f / NTOK) - m * m;
        s_mean = m;
        s_rstd = rsqrtf(v + 1e-5f);
    }
    __syncthreads();
    const float m = s_mean, r = s_rstd;
    float4* q = (float4*)(out + (size_t)c * NTOK);
    for (int i = threadIdx.x; i < NTOK / 4; i += 256) {
        float4 v = p[i];
        v.x = (v.x - m) * r; v.y = (v.y - m) * r;
        v.z = (v.z - m) * r; v.w = (v.w - m) * r;
        q[i] = v;
    }
}

// ---------------- launch ------------------------------------------------------
extern "C" void kernel_launch(void* const* d_in, const int* in_sizes, int n_in,
                              void* d_out, int out_size)
{
    (void)in_sizes; (void)n_in; (void)out_size;
    const float* x      = (const float*)d_in[0];
    const float* w_qkv  = (const float*)d_in[1];
    const float* b_qkv  = (const float*)d_in[2];
    const float* rpb    = (const float*)d_in[3];
    const float* w_proj = (const float*)d_in[4];
    const float* b_proj = (const float*)d_in[5];
    const float* w_ffn1 = (const float*)d_in[6];
    const float* b_ffn1 = (const float*)d_in[7];
    const float* w_ffn2 = (const float*)d_in[8];
    const float* b_ffn2 = (const float*)d_in[9];
    float* out = (float*)d_out;

    float *qkv, *attn, *x5, *t, *hid, *y;
    cudaGetSymbolAddress((void**)&qkv,  g_qkv);
    cudaGetSymbolAddress((void**)&attn, g_attn);
    cudaGetSymbolAddress((void**)&x5,   g_x5);
    cudaGetSymbolAddress((void**)&t,    g_t);
    cudaGetSymbolAddress((void**)&hid,  g_hid);
    cudaGetSymbolAddress((void**)&y,    g_y);

    // 1) QKV: [384][N]
    gemm_kn<0><<<dim3(NTOK / 64, 3), 256>>>(x, w_qkv, b_qkv, nullptr, qkv, CDIM);
    // 2) neighborhood attention -> [128][N]
    natten_kernel<<<1024, 256>>>(qkv, rpb, attn);
    // 3) proj -> [128][N]
    gemm_kn<0><<<dim3(NTOK / 64, 1), 256>>>(attn, w_proj, b_proj, nullptr, x5, CDIM);
    // 4) instance norm -> t
    inorm_kernel<<<CDIM, 256>>>(x5, t);
    // 5) FFN1 + GELU -> [512][N]
    gemm_kn<1><<<dim3(NTOK / 64, 4), 256>>>(t, w_ffn1, b_ffn1, nullptr, hid, CDIM);
    // 6) FFN2 + residual -> [128][N]
    gemm_kn<2><<<dim3(NTOK / 64, 1), 256>>>(hid, w_ffn2, b_ffn2, t, y, CF);
    // 7) final instance norm -> output (B,C,H,W,Z) == [c][n]
    inorm_kernel<<<CDIM, 256>>>(y, out);
}

// round 3
// speedup vs baseline: 1.7030x; 1.7030x over previous
#include <cuda_runtime.h>
#include <cuda_bf16.h>
#include <math.h>

#define NTOK 32768      // 32*32*32
#define CDIM 128
#define HEADS 8
#define HD 16
#define CF 512

// ---------------- scratch (device globals; no runtime allocation) ------------
__device__ float g_qkv [384 * NTOK];   // [j][n] j: 0-127 q, 128-255 k, 256-383 v
__device__ float g_attn[CDIM * NTOK];  // [c][n]
__device__ float g_x5  [CDIM * NTOK];  // [c][n] proj out
__device__ float g_t   [CDIM * NTOK];  // [c][n] normalized (FFN input + residual)
__device__ float g_hid [CF   * NTOK];  // [f][n]
__device__ float g_y   [CDIM * NTOK];  // [c][n] pre-final-IN

__device__ __forceinline__ float gelu_f(float x) {
    const float k0 = 0.7978845608028654f;   // sqrt(2/pi)
    const float k1 = 0.044715f;
    return 0.5f * x * (1.0f + tanhf(k0 * (x + k1 * x * x * x)));
}

// split a pair of fp32 into packed bf16x2 hi and lo parts
__device__ __forceinline__ void split2(float v0, float v1, unsigned &hi, unsigned &lo) {
    __nv_bfloat16 h0 = __float2bfloat16_rn(v0);
    __nv_bfloat16 h1 = __float2bfloat16_rn(v1);
    float r0 = v0 - __bfloat162float(h0);
    float r1 = v1 - __bfloat162float(h1);
    __nv_bfloat16 l0 = __float2bfloat16_rn(r0);
    __nv_bfloat16 l1 = __float2bfloat16_rn(r1);
    hi = (unsigned)__bfloat16_as_ushort(h0) | ((unsigned)__bfloat16_as_ushort(h1) << 16);
    lo = (unsigned)__bfloat16_as_ushort(l0) | ((unsigned)__bfloat16_as_ushort(l1) << 16);
}

__device__ __forceinline__ void ldsm4(unsigned &r0, unsigned &r1, unsigned &r2, unsigned &r3, unsigned addr) {
    asm volatile("ldmatrix.sync.aligned.m8n8.x4.shared.b16 {%0,%1,%2,%3}, [%4];"
                 : "=r"(r0), "=r"(r1), "=r"(r2), "=r"(r3) : "r"(addr));
}
__device__ __forceinline__ void ldsm4t(unsigned &r0, unsigned &r1, unsigned &r2, unsigned &r3, unsigned addr) {
    asm volatile("ldmatrix.sync.aligned.m8n8.x4.trans.shared.b16 {%0,%1,%2,%3}, [%4];"
                 : "=r"(r0), "=r"(r1), "=r"(r2), "=r"(r3) : "r"(addr));
}
__device__ __forceinline__ void mma_bf16(float *c, const unsigned *a, const unsigned *b) {
    asm volatile("mma.sync.aligned.m16n8k16.row.col.f32.bf16.bf16.f32 "
                 "{%0,%1,%2,%3},{%4,%5,%6,%7},{%8,%9},{%0,%1,%2,%3};"
                 : "+f"(c[0]), "+f"(c[1]), "+f"(c[2]), "+f"(c[3])
                 : "r"(a[0]), "r"(a[1]), "r"(a[2]), "r"(a[3]), "r"(b[0]), "r"(b[1]));
}

// ---------------- tensor-core GEMM: out[j][n] = sum_k W[j][k]*A[k][n] + b[j] --
// A k-major [Ktot][NTOK] fp32, W row-major [Jtot][Ktot] fp32.
// Split-bf16 (hi/lo) 3-mma emulation, fp32 accumulate.
// Tile: BM=64 (j) x BN=128 (n) x BK=32, 256 threads (8 warps: 2(M) x 4(N)).
// EPI: 0 = bias; 1 = gelu(bias+acc); 2 = residual R[j][n] + bias + acc
#define SW 40    // bf16 row stride of W tiles (32 + 8 pad)
#define SA 136   // bf16 row stride of A tiles (128 + 8 pad)

template<int EPI>
__global__ __launch_bounds__(256)
void gemm_tc(const float* __restrict__ A, const float* __restrict__ W,
             const float* __restrict__ bias, const float* __restrict__ R,
             float* __restrict__ out, int Ktot)
{
    __shared__ __align__(16) unsigned short sWh[64 * SW], sWl[64 * SW];
    __shared__ __align__(16) unsigned short sAh[32 * SA], sAl[32 * SA];

    const int tid  = threadIdx.x;
    const int lane = tid & 31;
    const int wid  = tid >> 5;
    const int wm   = wid >> 2;          // 0..1  (M warp)
    const int wn   = wid & 3;           // 0..3  (N warp)
    const int gid  = lane >> 2;         // 0..7
    const int tig  = lane & 3;          // 0..3
    const int lm   = lane & 15;
    const int lq   = lane >> 4;

    const int n0 = blockIdx.x * 128;
    const int j0 = blockIdx.y * 64;

    const unsigned bWh = (unsigned)__cvta_generic_to_shared(sWh);
    const unsigned bWl = (unsigned)__cvta_generic_to_shared(sWl);
    const unsigned bAh = (unsigned)__cvta_generic_to_shared(sAh);
    const unsigned bAl = (unsigned)__cvta_generic_to_shared(sAl);

    // fragment smem byte offsets
    unsigned aoff[2][2], boff[2][2];
    #pragma unroll
    for (int ma = 0; ma < 2; ma++)
        #pragma unroll
        for (int ka = 0; ka < 2; ka++)
            aoff[ma][ka] = ((wm * 32 + ma * 16 + lm) * SW + ka * 16 + lq * 8) * 2;
    #pragma unroll
    for (int p = 0; p < 2; p++)
        #pragma unroll
        for (int ka = 0; ka < 2; ka++)
            boff[p][ka] = ((ka * 16 + lm) * SA + wn * 32 + p * 16 + lq * 8) * 2;

    // loader indices
    const int wj  = (tid + 0) >> 3;        // base for i=0 (W)
    float acc[2][4][4];
    #pragma unroll
    for (int a = 0; a < 2; a++)
        #pragma unroll
        for (int b = 0; b < 4; b++)
            #pragma unroll
            for (int c = 0; c < 4; c++) acc[a][b][c] = 0.0f;

    float4 wreg[2], areg[4];

    auto load_tile = [&](int kc) {
        #pragma unroll
        for (int i = 0; i < 2; i++) {
            int flat = tid + i * 256;
            int j = flat >> 3, k4 = flat & 7;
            wreg[i] = *(const float4*)&W[(size_t)(j0 + j) * Ktot + kc + k4 * 4];
        }
        #pragma unroll
        for (int i = 0; i < 4; i++) {
            int flat = tid + i * 256;
            int k = flat >> 5, n4 = flat & 31;
            areg[i] = *(const float4*)&A[(size_t)(kc + k) * NTOK + n0 + n4 * 4];
        }
    };

    load_tile(0);

    for (int kc = 0; kc < Ktot; kc += 32) {
        // convert + store current tile to smem
        #pragma unroll
        for (int i = 0; i < 2; i++) {
            int flat = tid + i * 256;
            int j = flat >> 3, k4 = flat & 7;
            unsigned h0, l0, h1, l1;
            split2(wreg[i].x, wreg[i].y, h0, l0);
            split2(wreg[i].z, wreg[i].w, h1, l1);
            int widx = j * (SW / 2) + k4 * 2;
            ((unsigned*)sWh)[widx] = h0; ((unsigned*)sWh)[widx + 1] = h1;
            ((unsigned*)sWl)[widx] = l0; ((unsigned*)sWl)[widx + 1] = l1;
        }
        #pragma unroll
        for (int i = 0; i < 4; i++) {
            int flat = tid + i * 256;
            int k = flat >> 5, n4 = flat & 31;
            unsigned h0, l0, h1, l1;
            split2(areg[i].x, areg[i].y, h0, l0);
            split2(areg[i].z, areg[i].w, h1, l1);
            int widx = k * (SA / 2) + n4 * 2;
            ((unsigned*)sAh)[widx] = h0; ((unsigned*)sAh)[widx + 1] = h1;
            ((unsigned*)sAl)[widx] = l0; ((unsigned*)sAl)[widx + 1] = l1;
        }
        __syncthreads();

        if (kc + 32 < Ktot) load_tile(kc + 32);   // overlap LDG with compute

        #pragma unroll
        for (int ka = 0; ka < 2; ka++) {
            unsigned ah[2][4], al[2][4], bh[4][2], bl[4][2];
            #pragma unroll
            for (int ma = 0; ma < 2; ma++) {
                ldsm4(ah[ma][0], ah[ma][1], ah[ma][2], ah[ma][3], bWh + aoff[ma][ka]);
                ldsm4(al[ma][0], al[ma][1], al[ma][2], al[ma][3], bWl + aoff[ma][ka]);
            }
            #pragma unroll
            for (int p = 0; p < 2; p++) {
                unsigned r0, r1, r2, r3;
                ldsm4t(r0, r1, r2, r3, bAh + boff[p][ka]);
                bh[2 * p][0] = r0; bh[2 * p][1] = r1;
                bh[2 * p + 1][0] = r2; bh[2 * p + 1][1] = r3;
                ldsm4t(r0, r1, r2, r3, bAl + boff[p][ka]);
                bl[2 * p][0] = r0; bl[2 * p][1] = r1;
                bl[2 * p + 1][0] = r2; bl[2 * p + 1][1] = r3;
            }
            #pragma unroll
            for (int ma = 0; ma < 2; ma++)
                #pragma unroll
                for (int na = 0; na < 4; na++) {
                    mma_bf16(acc[ma][na], ah[ma], bh[na]);
                    mma_bf16(acc[ma][na], ah[ma], bl[na]);
                    mma_bf16(acc[ma][na], al[ma], bh[na]);
                }
        }
        __syncthreads();
    }

    // epilogue
    #pragma unroll
    for (int ma = 0; ma < 2; ma++) {
        int jA = j0 + wm * 32 + ma * 16 + gid;
        int jB = jA + 8;
        float bA = bias[jA], bB = bias[jB];
        #pragma unroll
        for (int na = 0; na < 4; na++) {
            int n = n0 + wn * 32 + na * 8 + tig * 2;
            float v0 = acc[ma][na][0] + bA;
            float v1 = acc[ma][na][1] + bA;
            float v2 = acc[ma][na][2] + bB;
            float v3 = acc[ma][na][3] + bB;
            if (EPI == 1) {
                v0 = gelu_f(v0); v1 = gelu_f(v1); v2 = gelu_f(v2); v3 = gelu_f(v3);
            }
            if (EPI == 2) {
                float2 rA = *(const float2*)&R[(size_t)jA * NTOK + n];
                float2 rB = *(const float2*)&R[(size_t)jB * NTOK + n];
                v0 += rA.x; v1 += rA.y; v2 += rB.x; v3 += rB.y;
            }
            float2 oA = {v0, v1}, oB = {v2, v3};
            *(float2*)&out[(size_t)jA * NTOK + n] = oA;
            *(float2*)&out[(size_t)jB * NTOK + n] = oB;
        }
    }
}

// ---------------- neighborhood attention (K=3, 27 taps) ----------------------
__global__ __launch_bounds__(256)
void natten_kernel(const float* __restrict__ qkv,
                   const float* __restrict__ rpb,
                   float* __restrict__ out)
{
    const int lane = threadIdx.x & 31;
    const int h    = threadIdx.x >> 5;
    const int ih   = blockIdx.x >> 5;
    const int iw   = blockIdx.x & 31;
    const int iz   = lane;
    const int n    = (ih * 32 + iw) * 32 + iz;

    int sh = ih - 1; sh = sh < 0 ? 0 : (sh > 29 ? 29 : sh);
    int sw = iw - 1; sw = sw < 0 ? 0 : (sw > 29 ? 29 : sw);
    int sz = iz - 1; sz = sz < 0 ? 0 : (sz > 29 ? 29 : sz);

    const float scale = 0.25f;
    float q[HD];
    #pragma unroll
    for (int d = 0; d < HD; d++)
        q[d] = qkv[(size_t)(h * HD + d) * NTOK + n] * scale;

    float lg[27];
    float mx = -1e30f;
    #pragma unroll
    for (int a = 0; a < 3; a++)
    #pragma unroll
    for (int b = 0; b < 3; b++)
    #pragma unroll
    for (int c = 0; c < 3; c++) {
        int nh = sh + a, nw = sw + b, nz = sz + c;
        int nn = (nh * 32 + nw) * 32 + nz;
        float s = 0.0f;
        #pragma unroll
        for (int d = 0; d < HD; d++)
            s = fmaf(q[d], qkv[(size_t)(CDIM + h * HD + d) * NTOK + nn], s);
        int rh = nh - ih + 2, rw = nw - iw + 2, rz = nz - iz + 2;
        s += rpb[((h * 5 + rh) * 5 + rw) * 5 + rz];
        lg[(a * 3 + b) * 3 + c] = s;
        mx = fmaxf(mx, s);
    }

    float denom = 0.0f;
    #pragma unroll
    for (int i = 0; i < 27; i++) { lg[i] = __expf(lg[i] - mx); denom += lg[i]; }
    const float inv = 1.0f / denom;

    float o[HD];
    #pragma unroll
    for (int d = 0; d < HD; d++) o[d] = 0.0f;
    #pragma unroll
    for (int a = 0; a < 3; a++)
    #pragma unroll
    for (int b = 0; b < 3; b++)
    #pragma unroll
    for (int c = 0; c < 3; c++) {
        int nh = sh + a, nw = sw + b, nz = sz + c;
        int nn = (nh * 32 + nw) * 32 + nz;
        float w = lg[(a * 3 + b) * 3 + c] * inv;
        #pragma unroll
        for (int d = 0; d < HD; d++)
            o[d] = fmaf(w, qkv[(size_t)(2 * CDIM + h * HD + d) * NTOK + nn], o[d]);
    }
    #pragma unroll
    for (int d = 0; d < HD; d++)
        out[(size_t)(h * HD + d) * NTOK + n] = o[d];
}

// ---------------- instance norm over N per channel ----------------------------
__global__ __launch_bounds__(256)
void inorm_kernel(const float* __restrict__ in, float* __restrict__ out)
{
    const int c = blockIdx.x;
    const float4* p = (const float4*)(in + (size_t)c * NTOK);
    float s = 0.0f, s2 = 0.0f;
    for (int i = threadIdx.x; i < NTOK / 4; i += 256) {
        float4 v = p[i];
        s  += v.x + v.y + v.z + v.w;
        s2 += v.x * v.x + v.y * v.y + v.z * v.z + v.w * v.w;
    }
    __shared__ float rs[256], rq[256];
    rs[threadIdx.x] = s; rq[threadIdx.x] = s2;
    __syncthreads();
    for (int st = 128; st > 0; st >>= 1) {
        if (threadIdx.x < st) {
            rs[threadIdx.x] += rs[threadIdx.x + st];
            rq[threadIdx.x] += rq[threadIdx.x + st];
        }
        __syncthreads();
    }
    __shared__ float s_mean, s_rstd;
    if (threadIdx.x == 0) {
        float m = rs[0] * (1.0f / NTOK);
        float v = rq[0] * (1.0f / NTOK) - m * m;
        s_mean = m;
        s_rstd = rsqrtf(v + 1e-5f);
    }
    __syncthreads();
    const float m = s_mean, r = s_rstd;
    float4* q = (float4*)(out + (size_t)c * NTOK);
    for (int i = threadIdx.x; i < NTOK / 4; i += 256) {
        float4 v = p[i];
        v.x = (v.x - m) * r; v.y = (v.y - m) * r;
        v.z = (v.z - m) * r; v.w = (v.w - m) * r;
        q[i] = v;
    }
}

// ---------------- launch ------------------------------------------------------
extern "C" void kernel_launch(void* const* d_in, const int* in_sizes, int n_in,
                              void* d_out, int out_size)
{
    (void)in_sizes; (void)n_in; (void)out_size;
    const float* x      = (const float*)d_in[0];
    const float* w_qkv  = (const float*)d_in[1];
    const float* b_qkv  = (const float*)d_in[2];
    const float* rpb    = (const float*)d_in[3];
    const float* w_proj = (const float*)d_in[4];
    const float* b_proj = (const float*)d_in[5];
    const float* w_ffn1 = (const float*)d_in[6];
    const float* b_ffn1 = (const float*)d_in[7];
    const float* w_ffn2 = (const float*)d_in[8];
    const float* b_ffn2 = (const float*)d_in[9];
    float* out = (float*)d_out;

    float *qkv, *attn, *x5, *t, *hid, *y;
    cudaGetSymbolAddress((void**)&qkv,  g_qkv);
    cudaGetSymbolAddress((void**)&attn, g_attn);
    cudaGetSymbolAddress((void**)&x5,   g_x5);
    cudaGetSymbolAddress((void**)&t,    g_t);
    cudaGetSymbolAddress((void**)&hid,  g_hid);
    cudaGetSymbolAddress((void**)&y,    g_y);

    // 1) QKV: [384][N]
    gemm_tc<0><<<dim3(NTOK / 128, 384 / 64), 256>>>(x, w_qkv, b_qkv, nullptr, qkv, CDIM);
    // 2) neighborhood attention -> [128][N]
    natten_kernel<<<1024, 256>>>(qkv, rpb, attn);
    // 3) proj -> [128][N]
    gemm_tc<0><<<dim3(NTOK / 128, 128 / 64), 256>>>(attn, w_proj, b_proj, nullptr, x5, CDIM);
    // 4) instance norm -> t
    inorm_kernel<<<CDIM, 256>>>(x5, t);
    // 5) FFN1 + GELU -> [512][N]
    gemm_tc<1><<<dim3(NTOK / 128, 512 / 64), 256>>>(t, w_ffn1, b_ffn1, nullptr, hid, CDIM);
    // 6) FFN2 + residual -> [128][N]
    gemm_tc<2><<<dim3(NTOK / 128, 128 / 64), 256>>>(hid, w_ffn2, b_ffn2, t, y, CF);
    // 7) final instance norm -> output (B,C,H,W,Z) == [c][n]
    inorm_kernel<<<CDIM, 256>>>(y, out);
}